// round 2
// baseline (speedup 1.0000x reference)
#include <cuda_runtime.h>
#include <cstdint>

#define B_ 64
#define T_ 4096
#define H_ 128

// Scratch for layer-0 input projection (alloc-free rule: __device__ global).
__device__ float g_xp0[(size_t)B_ * T_ * H_];

// ---------------------------------------------------------------------------
// Packed fp32x2 FMA (Blackwell sm_100a+): d.lo=a.lo*b.lo+c.lo, d.hi likewise.
// ---------------------------------------------------------------------------
union F2U { float2 f; unsigned long long u; };

__device__ __forceinline__ float2 ffma2(float2 a, float2 b, float2 c) {
    F2U A, Bv, C, D;
    A.f = a; Bv.f = b; C.f = c;
    asm("fma.rn.f32x2 %0, %1, %2, %3;" : "=l"(D.u) : "l"(A.u), "l"(Bv.u), "l"(C.u));
    return D.f;
}

__device__ __forceinline__ float tanh_fast(float x) {
    // tanh(x) = (e^{2x}-1)/(e^{2x}+1); clamp so e^{2x} stays finite.
    float xc = fminf(fmaxf(x, -9.0f), 9.0f);
    float e = __expf(2.0f * xc);
    return __fdividef(e - 1.0f, e + 1.0f);
}

// ---------------------------------------------------------------------------
// Kernel A: xp0[m][j] = sum_d x[m][d] * W_ih0[j][d] + b_ih0[j] + b_hh0[j]
// M = B*T = 262144, N = K = 128. CTA tile 128x128, K-chunks of 32.
// f32x2 pairs two adjacent OUTPUT columns (same k), so acc lanes are final
// sums directly (no horizontal add).
// ---------------------------------------------------------------------------
__global__ void __launch_bounds__(512, 1) xp0_gemm(
    const float* __restrict__ x,
    const float* __restrict__ W_ih0,
    const float* __restrict__ b_ih0,
    const float* __restrict__ b_hh0)
{
    __shared__ float A_s[128][32];   // [row][k]   row-major
    __shared__ float W_s[32][128];   // [k][col]   k-major (transposed on load)

    const int tid  = threadIdx.x;
    const int m0   = blockIdx.x * 128;
    const int row0 = (tid >> 5) * 8;   // 16 row groups of 8
    const int col0 = (tid & 31) * 4;   // 32 col groups of 4

    float2 acc[8][2];
    #pragma unroll
    for (int i = 0; i < 8; i++) {
        acc[i][0] = make_float2(0.f, 0.f);
        acc[i][1] = make_float2(0.f, 0.f);
    }

    for (int kk = 0; kk < 128; kk += 32) {
        __syncthreads();
        // Load A tile: 128x32 floats = 1024 float4, 2 per thread (coalesced).
        #pragma unroll
        for (int l = 0; l < 2; l++) {
            int idx = tid + l * 512;
            int r = idx >> 3, q4 = idx & 7;
            float4 v = *(const float4*)(x + (size_t)(m0 + r) * 128 + kk + q4 * 4);
            *(float4*)&A_s[r][q4 * 4] = v;
        }
        // Load W tile transposed into k-major: 128x32 floats.
        #pragma unroll
        for (int l = 0; l < 2; l++) {
            int idx = tid + l * 512;          // 0..1023
            int j = idx & 127, q4 = idx >> 7; // q4: 0..7
            float4 v = *(const float4*)(W_ih0 + j * 128 + kk + q4 * 4);
            W_s[q4 * 4 + 0][j] = v.x;
            W_s[q4 * 4 + 1][j] = v.y;
            W_s[q4 * 4 + 2][j] = v.z;
            W_s[q4 * 4 + 3][j] = v.w;
        }
        __syncthreads();

        #pragma unroll
        for (int k4 = 0; k4 < 8; k4++) {
            float4 a[8];
            #pragma unroll
            for (int i = 0; i < 8; i++)
                a[i] = *(const float4*)&A_s[row0 + i][k4 * 4];   // broadcast
            #pragma unroll
            for (int u = 0; u < 4; u++) {
                float4 w = *(const float4*)&W_s[k4 * 4 + u][col0]; // conflict-free
                float2 wlo = make_float2(w.x, w.y);
                float2 whi = make_float2(w.z, w.w);
                #pragma unroll
                for (int i = 0; i < 8; i++) {
                    float av = (u == 0) ? a[i].x : (u == 1) ? a[i].y
                             : (u == 2) ? a[i].z : a[i].w;
                    float2 a2 = make_float2(av, av);
                    acc[i][0] = ffma2(a2, wlo, acc[i][0]);
                    acc[i][1] = ffma2(a2, whi, acc[i][1]);
                }
            }
        }
    }

    float4 bias;
    bias.x = b_ih0[col0 + 0] + b_hh0[col0 + 0];
    bias.y = b_ih0[col0 + 1] + b_hh0[col0 + 1];
    bias.z = b_ih0[col0 + 2] + b_hh0[col0 + 2];
    bias.w = b_ih0[col0 + 3] + b_hh0[col0 + 3];

    #pragma unroll
    for (int i = 0; i < 8; i++) {
        float4 o;
        o.x = acc[i][0].x + bias.x;
        o.y = acc[i][0].y + bias.y;
        o.z = acc[i][1].x + bias.z;
        o.w = acc[i][1].y + bias.w;
        *(float4*)(g_xp0 + (size_t)(m0 + row0 + i) * 128 + col0) = o;
    }
}

// ---------------------------------------------------------------------------
// Kernel B: fused 2-layer recurrence. 1 CTA per batch, 256 threads.
// Thread (j = tid>>1, c = tid&1) owns output row j, k-half c (64 k's).
// All three weight rows (W_hh0, W_ih1, W_hh1) held in registers as float2
// pairs along k. h vectors in double-buffered smem, read as broadcast LDS.128.
// out0 is never written to global; xp0 prefetched 2 steps ahead.
// ---------------------------------------------------------------------------
__global__ void __launch_bounds__(256, 1) rnn_recurrence(
    const float* __restrict__ W_hh0,
    const float* __restrict__ W_ih1,
    const float* __restrict__ W_hh1,
    const float* __restrict__ b_ih1,
    const float* __restrict__ b_hh1,
    float* __restrict__ out1,     // [B,T,H]
    float* __restrict__ hidden)   // [2,B,H]
{
    __shared__ float h0s[2][128];
    __shared__ float h1s[2][128];

    const int b   = blockIdx.x;
    const int tid = threadIdx.x;
    const int j   = tid >> 1;
    const int c   = tid & 1;

    // Weight rows -> registers (3 * 32 float2 = 192 regs).
    float2 w0[32], wi[32], wh[32];
    {
        const float2* p0 = (const float2*)(W_hh0 + j * 128 + c * 64);
        const float2* p1 = (const float2*)(W_ih1 + j * 128 + c * 64);
        const float2* p2 = (const float2*)(W_hh1 + j * 128 + c * 64);
        #pragma unroll
        for (int i = 0; i < 32; i++) { w0[i] = p0[i]; wi[i] = p1[i]; wh[i] = p2[i]; }
    }
    const float bias1 = b_ih1[j] + b_hh1[j];

    if (tid < 128) { h0s[0][tid] = 0.f; h1s[0][tid] = 0.f; }

    const float* xp = g_xp0 + (size_t)b * T_ * H_ + j;
    float xpA = __ldcg(&xp[0]);
    float xpB = __ldcg(&xp[H_]);
    float* outb = out1 + (size_t)b * T_ * H_ + j;
    __syncthreads();

    int p = 0;
    #pragma unroll 1
    for (int t = 0; t < T_; t++) {
        // ---- phase 1: a = h0_old . w_hh0 ; g = h1_old . w_hh1 (overlapped) --
        const float4* hv0 = (const float4*)&h0s[p][c * 64];
        const float4* hv1 = (const float4*)&h1s[p][c * 64];
        float2 a0 = make_float2(0.f, 0.f), a1 = a0, a2 = a0, a3 = a0;
        float2 g0 = a0, g1 = a0, g2 = a0, g3 = a0;
        #pragma unroll
        for (int i = 0; i < 16; i += 2) {
            float4 hA = hv0[i], hB = hv0[i + 1];
            a0 = ffma2(make_float2(hA.x, hA.y), w0[2 * i + 0], a0);
            a1 = ffma2(make_float2(hA.z, hA.w), w0[2 * i + 1], a1);
            a2 = ffma2(make_float2(hB.x, hB.y), w0[2 * i + 2], a2);
            a3 = ffma2(make_float2(hB.z, hB.w), w0[2 * i + 3], a3);
        }
        #pragma unroll
        for (int i = 0; i < 16; i += 2) {
            float4 hA = hv1[i], hB = hv1[i + 1];
            g0 = ffma2(make_float2(hA.x, hA.y), wh[2 * i + 0], g0);
            g1 = ffma2(make_float2(hA.z, hA.w), wh[2 * i + 1], g1);
            g2 = ffma2(make_float2(hB.x, hB.y), wh[2 * i + 2], g2);
            g3 = ffma2(make_float2(hB.z, hB.w), wh[2 * i + 3], g3);
        }
        float s0 = ((a0.x + a0.y) + (a1.x + a1.y)) + ((a2.x + a2.y) + (a3.x + a3.y));
        s0 += __shfl_xor_sync(0xffffffffu, s0, 1);
        float h0new = tanh_fast(s0 + xpA);
        // rotate xp prefetch (distance 2 covers DRAM latency); clamped, branch-free
        xpA = xpB;
        {
            int tp = t + 2; tp = (tp < T_) ? tp : (T_ - 1);
            xpB = __ldcg(&xp[(size_t)tp * H_]);
        }
        h0s[p ^ 1][j] = h0new;
        __syncthreads();

        // ---- phase 2: s1 = h0_new . w_ih1 + g + bias1 -----------------------
        const float4* hn = (const float4*)&h0s[p ^ 1][c * 64];
        #pragma unroll
        for (int i = 0; i < 16; i += 2) {
            float4 hA = hn[i], hB = hn[i + 1];
            g0 = ffma2(make_float2(hA.x, hA.y), wi[2 * i + 0], g0);
            g1 = ffma2(make_float2(hA.z, hA.w), wi[2 * i + 1], g1);
            g2 = ffma2(make_float2(hB.x, hB.y), wi[2 * i + 2], g2);
            g3 = ffma2(make_float2(hB.z, hB.w), wi[2 * i + 3], g3);
        }
        float s1 = ((g0.x + g0.y) + (g1.x + g1.y)) + ((g2.x + g2.y) + (g3.x + g3.y));
        s1 += __shfl_xor_sync(0xffffffffu, s1, 1);
        float h1new = tanh_fast(s1 + bias1);
        h1s[p ^ 1][j] = h1new;
        if (c == 0) outb[(size_t)t * H_] = h1new;
        __syncthreads();
        p ^= 1;
    }

    if (c == 0) hidden[(size_t)b * H_ + j] = h0s[p][j];
    else        hidden[(size_t)B_ * H_ + b * H_ + j] = h1s[p][j];
}

// ---------------------------------------------------------------------------
// kernel_launch
// Inputs (metadata order): x, W_ih0, W_hh0, b_ih0, b_hh0, W_ih1, W_hh1,
//                          b_ih1, b_hh1.
// Output: out1 [B,T,H] followed by hidden_state [2,B,H].
// ---------------------------------------------------------------------------
extern "C" void kernel_launch(void* const* d_in, const int* in_sizes, int n_in,
                              void* d_out, int out_size) {
    const float* x      = (const float*)d_in[0];
    const float* W_ih0  = (const float*)d_in[1];
    const float* W_hh0  = (const float*)d_in[2];
    const float* b_ih0  = (const float*)d_in[3];
    const float* b_hh0  = (const float*)d_in[4];
    const float* W_ih1  = (const float*)d_in[5];
    const float* W_hh1  = (const float*)d_in[6];
    const float* b_ih1  = (const float*)d_in[7];
    const float* b_hh1  = (const float*)d_in[8];

    float* out1   = (float*)d_out;
    float* hidden = (float*)d_out + (size_t)B_ * T_ * H_;

    xp0_gemm<<<(B_ * T_) / 128, 512>>>(x, W_ih0, b_ih0, b_hh0);
    rnn_recurrence<<<B_, 256>>>(W_hh0, W_ih1, W_hh1, b_ih1, b_hh1, out1, hidden);
}

// round 4
// speedup vs baseline: 1.3975x; 1.3975x over previous
#include <cuda_runtime.h>
#include <cstdint>

#define B_ 64
#define T_ 4096
#define H_ 128

// Scratch for layer-0 input projection (alloc-free rule: __device__ global).
__device__ float g_xp0[(size_t)B_ * T_ * H_];

// ---------------------------------------------------------------------------
// Packed fp32x2 ops (Blackwell sm_100a+).
// ---------------------------------------------------------------------------
union F2U { float2 f; unsigned long long u; };

__device__ __forceinline__ float2 ffma2(float2 a, float2 b, float2 c) {
    F2U A, Bv, C, D;
    A.f = a; Bv.f = b; C.f = c;
    asm("fma.rn.f32x2 %0, %1, %2, %3;" : "=l"(D.u) : "l"(A.u), "l"(Bv.u), "l"(C.u));
    return D.f;
}

__device__ __forceinline__ float2 fadd2(float2 a, float2 b) {
    F2U A, Bv, D;
    A.f = a; Bv.f = b;
    asm("add.rn.f32x2 %0, %1, %2;" : "=l"(D.u) : "l"(A.u), "l"(Bv.u));
    return D.f;
}

__device__ __forceinline__ float tanh_fast(float x) {
    float xc = fminf(fmaxf(x, -9.0f), 9.0f);
    float e = __expf(2.0f * xc);
    return __fdividef(e - 1.0f, e + 1.0f);
}

// Full 128-length dot of a register-resident row (64 float2) with an smem
// vector read as 32 float4 broadcasts. 4 independent accumulator chains.
__device__ __forceinline__ float dot128(const float2* __restrict__ w,
                                        const float4* __restrict__ hv) {
    float2 a0 = make_float2(0.f, 0.f), a1 = a0, a2 = a0, a3 = a0;
    #pragma unroll
    for (int i = 0; i < 32; i += 2) {
        float4 hA = hv[i];
        float4 hB = hv[i + 1];
        a0 = ffma2(make_float2(hA.x, hA.y), w[2 * i + 0], a0);
        a1 = ffma2(make_float2(hA.z, hA.w), w[2 * i + 1], a1);
        a2 = ffma2(make_float2(hB.x, hB.y), w[2 * i + 2], a2);
        a3 = ffma2(make_float2(hB.z, hB.w), w[2 * i + 3], a3);
    }
    float2 t0 = fadd2(a0, a1);
    float2 t1 = fadd2(a2, a3);
    t0 = fadd2(t0, t1);
    return t0.x + t0.y;
}

// ---------------------------------------------------------------------------
// Kernel A: xp0 = x @ W_ih0^T + b_ih0 + b_hh0
// ---------------------------------------------------------------------------
__global__ void __launch_bounds__(512, 1) xp0_gemm(
    const float* __restrict__ x,
    const float* __restrict__ W_ih0,
    const float* __restrict__ b_ih0,
    const float* __restrict__ b_hh0)
{
    __shared__ float A_s[128][32];
    __shared__ float W_s[32][128];

    const int tid  = threadIdx.x;
    const int m0   = blockIdx.x * 128;
    const int row0 = (tid >> 5) * 8;
    const int col0 = (tid & 31) * 4;

    float2 acc[8][2];
    #pragma unroll
    for (int i = 0; i < 8; i++) {
        acc[i][0] = make_float2(0.f, 0.f);
        acc[i][1] = make_float2(0.f, 0.f);
    }

    for (int kk = 0; kk < 128; kk += 32) {
        __syncthreads();
        #pragma unroll
        for (int l = 0; l < 2; l++) {
            int idx = tid + l * 512;
            int r = idx >> 3, q4 = idx & 7;
            float4 v = *(const float4*)(x + (size_t)(m0 + r) * 128 + kk + q4 * 4);
            *(float4*)&A_s[r][q4 * 4] = v;
        }
        #pragma unroll
        for (int l = 0; l < 2; l++) {
            int idx = tid + l * 512;
            int j = idx & 127, q4 = idx >> 7;
            float4 v = *(const float4*)(W_ih0 + j * 128 + kk + q4 * 4);
            W_s[q4 * 4 + 0][j] = v.x;
            W_s[q4 * 4 + 1][j] = v.y;
            W_s[q4 * 4 + 2][j] = v.z;
            W_s[q4 * 4 + 3][j] = v.w;
        }
        __syncthreads();

        #pragma unroll
        for (int k4 = 0; k4 < 8; k4++) {
            float4 a[8];
            #pragma unroll
            for (int i = 0; i < 8; i++)
                a[i] = *(const float4*)&A_s[row0 + i][k4 * 4];
            #pragma unroll
            for (int u = 0; u < 4; u++) {
                float4 w = *(const float4*)&W_s[k4 * 4 + u][col0];
                float2 wlo = make_float2(w.x, w.y);
                float2 whi = make_float2(w.z, w.w);
                #pragma unroll
                for (int i = 0; i < 8; i++) {
                    float av = (u == 0) ? a[i].x : (u == 1) ? a[i].y
                             : (u == 2) ? a[i].z : a[i].w;
                    float2 a2 = make_float2(av, av);
                    acc[i][0] = ffma2(a2, wlo, acc[i][0]);
                    acc[i][1] = ffma2(a2, whi, acc[i][1]);
                }
            }
        }
    }

    float4 bias;
    bias.x = b_ih0[col0 + 0] + b_hh0[col0 + 0];
    bias.y = b_ih0[col0 + 1] + b_hh0[col0 + 1];
    bias.z = b_ih0[col0 + 2] + b_hh0[col0 + 2];
    bias.w = b_ih0[col0 + 3] + b_hh0[col0 + 3];

    #pragma unroll
    for (int i = 0; i < 8; i++) {
        float4 o;
        o.x = acc[i][0].x + bias.x;
        o.y = acc[i][0].y + bias.y;
        o.z = acc[i][1].x + bias.z;
        o.w = acc[i][1].y + bias.w;
        *(float4*)(g_xp0 + (size_t)(m0 + row0 + i) * 128 + col0) = o;
    }
}

// ---------------------------------------------------------------------------
// Kernel B: fused 2-layer recurrence, software-pipelined by matrix.
// 384 threads = 3 groups of 128; thread j of each group owns a full weight row
// (64 float2 in registers). ONE __syncthreads per step, NO shuffles.
//
// Iteration it (0 .. T+1), pr = it&1:
//   Group A (grp 0): h0[it]   = tanh(xp0[it] + h0[it-1]·W_hh0_row)   [it < T]
//                    reads h0s[pr], writes h0s[pr^1]
//   Group B (grp 1): D1[it-1] = h0[it-1]·W_ih1_row                   [1<=it<=T]
//                    reads h0s[pr], writes d1s[pr]
//   Group C (grp 2): h1[it-2] = tanh(b1 + D1[it-2] + h1[it-3]·W_hh1_row)
//                    reads h1s[pr^1], d1s[pr^1]; writes h1s[pr], out1[it-2]
// ---------------------------------------------------------------------------
__global__ void __launch_bounds__(384, 1) rnn_recurrence(
    const float* __restrict__ W_hh0,
    const float* __restrict__ W_ih1,
    const float* __restrict__ W_hh1,
    const float* __restrict__ b_ih1,
    const float* __restrict__ b_hh1,
    float* __restrict__ out1,     // [B,T,H]
    float* __restrict__ hidden)   // [2,B,H]
{
    __shared__ float h0s[2][128];
    __shared__ float h1s[2][128];
    __shared__ float d1s[2][128];

    const int b   = blockIdx.x;
    const int tid = threadIdx.x;
    const int grp = tid >> 7;     // 0=A, 1=B, 2=C (warp-group aligned)
    const int j   = tid & 127;

    if (tid < 128) {
        h0s[0][tid] = 0.f; h0s[1][tid] = 0.f;
        h1s[0][tid] = 0.f; h1s[1][tid] = 0.f;
        d1s[0][tid] = 0.f; d1s[1][tid] = 0.f;
    }

    // Per-group weight row -> 64 float2 registers.
    const float* wsrc = (grp == 0) ? (W_hh0 + j * 128)
                      : (grp == 1) ? (W_ih1 + j * 128)
                                   : (W_hh1 + j * 128);
    float2 w[64];
    {
        const float2* p = (const float2*)wsrc;
        #pragma unroll
        for (int i = 0; i < 64; i++) w[i] = p[i];
    }

    const float bias1 = b_ih1[j] + b_hh1[j];   // used by group C only

    // Group A xp0 prefetch state (distance 2).
    const float* xp = g_xp0 + (size_t)b * T_ * H_ + j;
    float xpA = 0.f, xpB = 0.f;
    if (grp == 0) { xpA = __ldcg(&xp[0]); xpB = __ldcg(&xp[H_]); }

    float* outb = out1 + (size_t)b * T_ * H_ + j;
    float h0_last = 0.f, h1_last = 0.f;

    __syncthreads();

    #pragma unroll 1
    for (int it = 0; it < T_ + 2; it++) {
        const int pr = it & 1;
        if (grp == 0) {
            if (it < T_) {
                float s = dot128(w, (const float4*)h0s[pr]);
                float h0new = tanh_fast(s + xpA);
                xpA = xpB;
                int tp = it + 2; tp = (tp < T_) ? tp : (T_ - 1);
                xpB = __ldcg(&xp[(size_t)tp * H_]);
                h0s[pr ^ 1][j] = h0new;
                h0_last = h0new;
            }
        } else if (grp == 1) {
            if (it >= 1 && it <= T_) {
                float s = dot128(w, (const float4*)h0s[pr]);
                d1s[pr][j] = s;
            }
        } else {
            if (it >= 2) {
                float s = dot128(w, (const float4*)h1s[pr ^ 1]);
                float h1new = tanh_fast(s + d1s[pr ^ 1][j] + bias1);
                h1s[pr][j] = h1new;
                __stcg(&outb[(size_t)(it - 2) * H_], h1new);
                h1_last = h1new;
            }
        }
        __syncthreads();
    }

    if (grp == 0) hidden[(size_t)b * H_ + j] = h0_last;
    if (grp == 2) hidden[(size_t)B_ * H_ + (size_t)b * H_ + j] = h1_last;
}

// ---------------------------------------------------------------------------
// kernel_launch
// Inputs (metadata order): x, W_ih0, W_hh0, b_ih0, b_hh0, W_ih1, W_hh1,
//                          b_ih1, b_hh1.
// Output: out1 [B,T,H] followed by hidden_state [2,B,H].
// ---------------------------------------------------------------------------
extern "C" void kernel_launch(void* const* d_in, const int* in_sizes, int n_in,
                              void* d_out, int out_size) {
    const float* x      = (const float*)d_in[0];
    const float* W_ih0  = (const float*)d_in[1];
    const float* W_hh0  = (const float*)d_in[2];
    const float* b_ih0  = (const float*)d_in[3];
    const float* b_hh0  = (const float*)d_in[4];
    const float* W_ih1  = (const float*)d_in[5];
    const float* W_hh1  = (const float*)d_in[6];
    const float* b_ih1  = (const float*)d_in[7];
    const float* b_hh1  = (const float*)d_in[8];

    float* out1   = (float*)d_out;
    float* hidden = (float*)d_out + (size_t)B_ * T_ * H_;

    xp0_gemm<<<(B_ * T_) / 128, 512>>>(x, W_ih0, b_ih0, b_hh0);
    rnn_recurrence<<<B_, 384>>>(W_hh0, W_ih1, W_hh1, b_ih1, b_hh1, out1, hidden);
}